// round 1
// baseline (speedup 1.0000x reference)
#include <cuda_runtime.h>

#define BB 1024
#define TT 512
#define H1C 80
#define G1 320
#define H2C 100
#define G2 400

// Scratch (static device arrays: allocation-free per harness rules)
__device__ float g_h1[(size_t)TT * BB * H1C];      // relu(h1) for all (t,b): 168 MB
__device__ float g_xg2[(size_t)TT * BB * G2];      // layer-2 gate pre-activations: 839 MB
__device__ float g_h2last[BB * H2C];               // relu(h2) at t=T-1

__device__ __forceinline__ float2 ffma2(float2 d, float2 a, float2 b) {
    unsigned long long dd = *reinterpret_cast<unsigned long long*>(&d);
    unsigned long long aa = *reinterpret_cast<unsigned long long*>(&a);
    unsigned long long bb = *reinterpret_cast<unsigned long long*>(&b);
    asm("fma.rn.f32x2 %0, %1, %2, %0;" : "+l"(dd) : "l"(aa), "l"(bb));
    return *reinterpret_cast<float2*>(&dd);
}

__device__ __forceinline__ float sigm(float x) { return 1.0f / (1.0f + __expf(-x)); }
__device__ __forceinline__ float tanh_(float x) { return 2.0f / (1.0f + __expf(-2.0f * x)) - 1.0f; }

// ---------------------------------------------------------------------------
// Kernel 1: layer-1 LSTM recurrence. 128 blocks x 8 batches, persistent over T.
// SMEM: Wt1[80][320] (W_hh1 transposed), wx[320], bias[320], h1s[80][8],
//       c1s[640], gs[8][320], xall[8][512]
// ---------------------------------------------------------------------------
__global__ void __launch_bounds__(256, 1)
lstm1_kernel(const float* __restrict__ x, const float* __restrict__ W_ih1,
             const float* __restrict__ W_hh1, const float* __restrict__ b_ih1,
             const float* __restrict__ b_hh1) {
    extern __shared__ float sm[];
    float* Wt   = sm;               // 25600
    float* wx   = Wt + 25600;       // 320
    float* bs   = wx + 320;         // 320
    float* h1s  = bs + 320;         // 640  [k][b]
    float* c1s  = h1s + 640;        // 640  [b*80+u]
    float* gs   = c1s + 640;        // 2560 [b][320]
    float* xall = gs + 2560;        // 4096 [b][t]

    const int tid = threadIdx.x;
    const int b0  = blockIdx.x * 8;

    for (int i = tid; i < G1 * H1C; i += 256) {
        int j = i / H1C, k = i - j * H1C;
        Wt[k * G1 + j] = W_hh1[i];
    }
    for (int i = tid; i < G1; i += 256) { wx[i] = W_ih1[i]; bs[i] = b_ih1[i] + b_hh1[i]; }
    for (int i = tid; i < 640; i += 256) { h1s[i] = 0.0f; c1s[i] = 0.0f; }
    for (int i = tid; i < 8 * TT; i += 256) {
        int b = i / TT, t = i - b * TT;
        xall[i] = x[(size_t)(b0 + b) * TT + t];
    }
    __syncthreads();

    const int kg = tid >> 7;          // k-split: 0 -> k[0,40), 1 -> k[40,80)
    const int jg = tid & 127;         // row group; active if jg < 80
    const int j  = jg * 4;

    for (int t = 0; t < TT; ++t) {
        float2 a0[8], a1[8];
        if (jg < 80) {
#pragma unroll
            for (int b = 0; b < 8; ++b) { a0[b] = make_float2(0.f, 0.f); a1[b] = make_float2(0.f, 0.f); }
            const float* wp = Wt + kg * 40 * G1 + j;
            const float* hp = h1s + kg * 40 * 8;
#pragma unroll 2
            for (int k = 0; k < 40; ++k) {
                float4 ha = *(const float4*)(hp + k * 8);
                float4 hb = *(const float4*)(hp + k * 8 + 4);
                float2 w0 = *(const float2*)(wp + k * G1);
                float2 w1 = *(const float2*)(wp + k * G1 + 2);
                float hv[8] = {ha.x, ha.y, ha.z, ha.w, hb.x, hb.y, hb.z, hb.w};
#pragma unroll
                for (int b = 0; b < 8; ++b) {
                    float2 hd = make_float2(hv[b], hv[b]);
                    a0[b] = ffma2(a0[b], w0, hd);
                    a1[b] = ffma2(a1[b], w1, hd);
                }
            }
            if (kg) {
#pragma unroll
                for (int b = 0; b < 8; ++b) {
                    *(float2*)(gs + b * G1 + j)     = a0[b];
                    *(float2*)(gs + b * G1 + j + 2) = a1[b];
                }
            }
        }
        __syncthreads();
        if (kg == 0 && jg < 80) {
#pragma unroll
            for (int b = 0; b < 8; ++b) {
                float xb = xall[b * TT + t];
                float* gp = gs + b * G1 + j;
                gp[0] = gp[0] + a0[b].x + xb * wx[j]     + bs[j];
                gp[1] = gp[1] + a0[b].y + xb * wx[j + 1] + bs[j + 1];
                gp[2] = gp[2] + a1[b].x + xb * wx[j + 2] + bs[j + 2];
                gp[3] = gp[3] + a1[b].y + xb * wx[j + 3] + bs[j + 3];
            }
        }
        __syncthreads();
        for (int item = tid; item < 640; item += 256) {
            int b = item / 80, u = item - b * 80;
            const float* gp = gs + b * G1;
            float ig = sigm(gp[u]);
            float fg = sigm(gp[80 + u]);
            float gg = tanh_(gp[160 + u]);
            float og = sigm(gp[240 + u]);
            float c = fg * c1s[item] + ig * gg;
            c1s[item] = c;
            float h = og * tanh_(c);
            h1s[u * 8 + b] = h;
            g_h1[(size_t)t * (BB * H1C) + (size_t)(b0 + b) * H1C + u] = fmaxf(h, 0.0f);
        }
        __syncthreads();
    }
}

// ---------------------------------------------------------------------------
// Kernel 2: xg2 = relu(h1) @ W_ih2^T + (b_ih2 + b_hh2).  Persistent, 148 blocks.
// Rows R = T*B = 524288, tile 32 rows/iter, thread tile 8x8.
// ---------------------------------------------------------------------------
__global__ void __launch_bounds__(256, 1)
xg2_gemm_kernel(const float* __restrict__ W_ih2, const float* __restrict__ b_ih2,
                const float* __restrict__ b_hh2) {
    extern __shared__ float sm[];
    float* Wt   = sm;            // 80*400 = 32000 (transposed W_ih2)
    float* bias = Wt + 32000;    // 400
    float* As   = bias + 400;    // 32*80 = 2560

    const int tid = threadIdx.x;
    for (int i = tid; i < G2 * H1C; i += 256) {
        int jj = i / H1C, k = i - jj * H1C;
        Wt[k * G2 + jj] = W_ih2[i];
    }
    for (int i = tid; i < G2; i += 256) bias[i] = b_ih2[i] + b_hh2[i];

    const int  rg  = tid / 50;
    const int  cg  = tid - rg * 50;
    const bool act = tid < 200;
    const int  NT  = (TT * BB) / 32;   // 16384 tiles

    for (int tile = blockIdx.x; tile < NT; tile += gridDim.x) {
        size_t r0 = (size_t)tile * 32;
        __syncthreads();
        for (int i = tid; i < 32 * H1C; i += 256) As[i] = g_h1[r0 * H1C + i];
        __syncthreads();
        if (act) {
            float2 acc[8][4];
#pragma unroll
            for (int i = 0; i < 8; ++i)
#pragma unroll
                for (int p = 0; p < 4; ++p) acc[i][p] = make_float2(0.f, 0.f);
            const float* ap = As + rg * 8 * H1C;
            const float* wp = Wt + cg * 8;
#pragma unroll 2
            for (int k = 0; k < H1C; ++k) {
                float2 w0 = *(const float2*)(wp + k * G2);
                float2 w1 = *(const float2*)(wp + k * G2 + 2);
                float2 w2 = *(const float2*)(wp + k * G2 + 4);
                float2 w3 = *(const float2*)(wp + k * G2 + 6);
#pragma unroll
                for (int i = 0; i < 8; ++i) {
                    float a = ap[i * H1C + k];
                    float2 ad = make_float2(a, a);
                    acc[i][0] = ffma2(acc[i][0], w0, ad);
                    acc[i][1] = ffma2(acc[i][1], w1, ad);
                    acc[i][2] = ffma2(acc[i][2], w2, ad);
                    acc[i][3] = ffma2(acc[i][3], w3, ad);
                }
            }
            const int c = cg * 8;
#pragma unroll
            for (int i = 0; i < 8; ++i) {
                size_t row = r0 + (size_t)rg * 8 + i;
                float* op = g_xg2 + row * G2 + c;
#pragma unroll
                for (int p = 0; p < 4; ++p) {
                    float2 v = acc[i][p];
                    v.x += bias[c + 2 * p];
                    v.y += bias[c + 2 * p + 1];
                    *(float2*)(op + 2 * p) = v;
                }
            }
        }
    }
}

// ---------------------------------------------------------------------------
// Kernel 3: layer-2 LSTM recurrence. 128 blocks x 8 batches, persistent over T.
// SMEM: Wt2[100][400] (W_hh2 transposed, 160KB), h2s[100][8], c2s[800], gs[8][400]
// ---------------------------------------------------------------------------
__global__ void __launch_bounds__(256, 1)
lstm2_kernel(const float* __restrict__ W_hh2) {
    extern __shared__ float sm[];
    float* Wt  = sm;              // 40000
    float* h2s = Wt + 40000;      // 800  [k][b]
    float* c2s = h2s + 800;       // 800
    float* gs  = c2s + 800;       // 3200 [b][400]

    const int tid = threadIdx.x;
    const int b0  = blockIdx.x * 8;

    for (int i = tid; i < G2 * H2C; i += 256) {
        int jj = i / H2C, k = i - jj * H2C;
        Wt[k * G2 + jj] = W_hh2[i];
    }
    for (int i = tid; i < 800; i += 256) { h2s[i] = 0.0f; c2s[i] = 0.0f; }
    __syncthreads();

    const int kg = tid >> 7;      // k-split: 0 -> k[0,50), 1 -> k[50,100)
    const int jg = tid & 127;     // active if jg < 100
    const int j  = jg * 4;

    for (int t = 0; t < TT; ++t) {
        float4 xg[8];
        if (kg == 0 && jg < 100) {   // prefetch gate pre-activations (latency hidden by k-loop)
            const float* xp = g_xg2 + (size_t)t * (BB * G2) + (size_t)b0 * G2 + j;
#pragma unroll
            for (int b = 0; b < 8; ++b) xg[b] = *(const float4*)(xp + b * G2);
        }
        float2 a0[8], a1[8];
        if (jg < 100) {
#pragma unroll
            for (int b = 0; b < 8; ++b) { a0[b] = make_float2(0.f, 0.f); a1[b] = make_float2(0.f, 0.f); }
            const float* wp = Wt + kg * 50 * G2 + j;
            const float* hp = h2s + kg * 50 * 8;
#pragma unroll 2
            for (int k = 0; k < 50; ++k) {
                float4 ha = *(const float4*)(hp + k * 8);
                float4 hb = *(const float4*)(hp + k * 8 + 4);
                float2 w0 = *(const float2*)(wp + k * G2);
                float2 w1 = *(const float2*)(wp + k * G2 + 2);
                float hv[8] = {ha.x, ha.y, ha.z, ha.w, hb.x, hb.y, hb.z, hb.w};
#pragma unroll
                for (int b = 0; b < 8; ++b) {
                    float2 hd = make_float2(hv[b], hv[b]);
                    a0[b] = ffma2(a0[b], w0, hd);
                    a1[b] = ffma2(a1[b], w1, hd);
                }
            }
            if (kg) {
#pragma unroll
                for (int b = 0; b < 8; ++b) {
                    *(float2*)(gs + b * G2 + j)     = a0[b];
                    *(float2*)(gs + b * G2 + j + 2) = a1[b];
                }
            }
        }
        __syncthreads();
        if (kg == 0 && jg < 100) {
#pragma unroll
            for (int b = 0; b < 8; ++b) {
                float* gp = gs + b * G2 + j;
                gp[0] = gp[0] + a0[b].x + xg[b].x;
                gp[1] = gp[1] + a0[b].y + xg[b].y;
                gp[2] = gp[2] + a1[b].x + xg[b].z;
                gp[3] = gp[3] + a1[b].y + xg[b].w;
            }
        }
        __syncthreads();
        for (int item = tid; item < 800; item += 256) {
            int b = item / 100, u = item - b * 100;
            const float* gp = gs + b * G2;
            float ig = sigm(gp[u]);
            float fg = sigm(gp[100 + u]);
            float gg = tanh_(gp[200 + u]);
            float og = sigm(gp[300 + u]);
            float c = fg * c2s[item] + ig * gg;
            c2s[item] = c;
            float h = og * tanh_(c);
            h2s[u * 8 + b] = h;
            if (t == TT - 1) g_h2last[(b0 + b) * H2C + u] = fmaxf(h, 0.0f);
        }
        __syncthreads();
    }
}

// ---------------------------------------------------------------------------
// Kernel 4: final MLP head. out[b] = W_l2 @ relu(W_l1 @ h + b_l1) + b_l2
// ---------------------------------------------------------------------------
__global__ void fc_kernel(const float* __restrict__ W_l1, const float* __restrict__ b_l1,
                          const float* __restrict__ W_l2, const float* __restrict__ b_l2,
                          float* __restrict__ out) {
    __shared__ float wl1[10 * 100];
    __shared__ float bl1[10], wl2[10], bl2s;
    const int tid = threadIdx.x;
    for (int i = tid; i < 1000; i += 256) wl1[i] = W_l1[i];
    if (tid < 10) { bl1[tid] = b_l1[tid]; wl2[tid] = W_l2[tid]; }
    if (tid == 0) bl2s = b_l2[0];
    __syncthreads();

    const int b = blockIdx.x * 256 + tid;
    float acc[10];
#pragma unroll
    for (int jj = 0; jj < 10; ++jj) acc[jj] = bl1[jj];
    const float* hp = g_h2last + b * H2C;
    for (int k = 0; k < H2C; ++k) {
        float hk = hp[k];
#pragma unroll
        for (int jj = 0; jj < 10; ++jj) acc[jj] = fmaf(wl1[jj * 100 + k], hk, acc[jj]);
    }
    float o = bl2s;
#pragma unroll
    for (int jj = 0; jj < 10; ++jj) o += wl2[jj] * fmaxf(acc[jj], 0.0f);
    out[b] = o;
}

// ---------------------------------------------------------------------------
extern "C" void kernel_launch(void* const* d_in, const int* in_sizes, int n_in,
                              void* d_out, int out_size) {
    const float* x     = (const float*)d_in[0];
    const float* W_ih1 = (const float*)d_in[1];
    const float* W_hh1 = (const float*)d_in[2];
    const float* b_ih1 = (const float*)d_in[3];
    const float* b_hh1 = (const float*)d_in[4];
    const float* W_ih2 = (const float*)d_in[5];
    const float* W_hh2 = (const float*)d_in[6];
    const float* b_ih2 = (const float*)d_in[7];
    const float* b_hh2 = (const float*)d_in[8];
    const float* W_l1  = (const float*)d_in[9];
    const float* b_l1  = (const float*)d_in[10];
    const float* W_l2  = (const float*)d_in[11];
    const float* b_l2  = (const float*)d_in[12];

    const size_t smA = (size_t)(25600 + 320 + 320 + 640 + 640 + 2560 + 4096) * 4;  // 136704 B
    const size_t smG = (size_t)(32000 + 400 + 2560) * 4;                            // 139840 B
    const size_t smB = (size_t)(40000 + 800 + 800 + 3200) * 4;                      // 179200 B

    cudaFuncSetAttribute(lstm1_kernel,    cudaFuncAttributeMaxDynamicSharedMemorySize, (int)smA);
    cudaFuncSetAttribute(xg2_gemm_kernel, cudaFuncAttributeMaxDynamicSharedMemorySize, (int)smG);
    cudaFuncSetAttribute(lstm2_kernel,    cudaFuncAttributeMaxDynamicSharedMemorySize, (int)smB);

    lstm1_kernel<<<128, 256, smA>>>(x, W_ih1, W_hh1, b_ih1, b_hh1);
    xg2_gemm_kernel<<<148, 256, smG>>>(W_ih2, b_ih2, b_hh2);
    lstm2_kernel<<<128, 256, smB>>>(W_hh2);
    fc_kernel<<<4, 256>>>(W_l1, b_l1, W_l2, b_l2, (float*)d_out);
}